// round 1
// baseline (speedup 1.0000x reference)
#include <cuda_runtime.h>
#include <math.h>

#define NTOK 16384   // B*T = 4*4096
#define DDIM 1024
#define NEXP 8
#define HDIM 512

// ---- device scratch (static allocs allowed) ----
__device__ int   g_counts[NEXP];
__device__ int   g_tok [NEXP * NTOK];
__device__ float g_gate[NEXP * NTOK];
__device__ float g_hidden[(size_t)NEXP * NTOK * HDIM];   // 256 MB worst-case capacity

// ============================================================
// Kernel 0: zero the output and the per-expert counters
// ============================================================
__global__ void init_kernel(float* __restrict__ out) {
    size_t i = (size_t)blockIdx.x * blockDim.x + threadIdx.x;
    if (i < (size_t)NTOK * DDIM / 4) {
        ((float4*)out)[i] = make_float4(0.f, 0.f, 0.f, 0.f);
    }
    if (blockIdx.x == 0 && threadIdx.x < NEXP) g_counts[threadIdx.x] = 0;
}

// ============================================================
// Kernel 1: router — one warp per token
// noisy = x@Wr + br + noise * softplus(x@Wn + bn); top-2; softmax gates
// ============================================================
__global__ void router_kernel(const float* __restrict__ x,
                              const float* __restrict__ Wr, const float* __restrict__ br,
                              const float* __restrict__ Wn, const float* __restrict__ bn,
                              const float* __restrict__ noise) {
    int gwarp = (blockIdx.x * blockDim.x + threadIdx.x) >> 5;
    int lane  = threadIdx.x & 31;
    if (gwarp >= NTOK) return;
    const float* xr = x + (size_t)gwarp * DDIM;

    float accL[NEXP], accN[NEXP];
#pragma unroll
    for (int e = 0; e < NEXP; e++) { accL[e] = 0.f; accN[e] = 0.f; }

    for (int d = lane; d < DDIM; d += 32) {
        float  xv = xr[d];
        float4 r0 = ((const float4*)(Wr + (size_t)d * NEXP))[0];
        float4 r1 = ((const float4*)(Wr + (size_t)d * NEXP))[1];
        float4 n0 = ((const float4*)(Wn + (size_t)d * NEXP))[0];
        float4 n1 = ((const float4*)(Wn + (size_t)d * NEXP))[1];
        accL[0] = fmaf(xv, r0.x, accL[0]);
        accL[1] = fmaf(xv, r0.y, accL[1]);
        accL[2] = fmaf(xv, r0.z, accL[2]);
        accL[3] = fmaf(xv, r0.w, accL[3]);
        accL[4] = fmaf(xv, r1.x, accL[4]);
        accL[5] = fmaf(xv, r1.y, accL[5]);
        accL[6] = fmaf(xv, r1.z, accL[6]);
        accL[7] = fmaf(xv, r1.w, accL[7]);
        accN[0] = fmaf(xv, n0.x, accN[0]);
        accN[1] = fmaf(xv, n0.y, accN[1]);
        accN[2] = fmaf(xv, n0.z, accN[2]);
        accN[3] = fmaf(xv, n0.w, accN[3]);
        accN[4] = fmaf(xv, n1.x, accN[4]);
        accN[5] = fmaf(xv, n1.y, accN[5]);
        accN[6] = fmaf(xv, n1.z, accN[6]);
        accN[7] = fmaf(xv, n1.w, accN[7]);
    }

    // warp reduce all 16 accumulators
#pragma unroll
    for (int off = 16; off > 0; off >>= 1) {
#pragma unroll
        for (int e = 0; e < NEXP; e++) {
            accL[e] += __shfl_down_sync(0xffffffffu, accL[e], off);
            accN[e] += __shfl_down_sync(0xffffffffu, accN[e], off);
        }
    }

    if (lane == 0) {
        float noisy[NEXP];
#pragma unroll
        for (int e = 0; e < NEXP; e++) {
            float nl = accN[e] + bn[e];
            // numerically stable softplus = log1p(exp(x))
            float sp = fmaxf(nl, 0.f) + log1pf(expf(-fabsf(nl)));
            noisy[e] = accL[e] + br[e] + noise[(size_t)gwarp * NEXP + e] * sp;
        }
        // top-2 (first occurrence wins ties, matching lax.top_k)
        int i1 = 0; float v1 = noisy[0];
#pragma unroll
        for (int e = 1; e < NEXP; e++) if (noisy[e] > v1) { v1 = noisy[e]; i1 = e; }
        int i2 = -1; float v2 = -3.4e38f;
#pragma unroll
        for (int e = 0; e < NEXP; e++) if (e != i1 && noisy[e] > v2) { v2 = noisy[e]; i2 = e; }

        // softmax over the two selected (others are -inf -> 0)
        float e1 = 1.0f;                 // exp(v1 - v1)
        float e2 = expf(v2 - v1);
        float s  = e1 + e2;
        float g1 = e1 / s;
        float g2 = e2 / s;

        int p1 = atomicAdd(&g_counts[i1], 1);
        g_tok [i1 * NTOK + p1] = gwarp;
        g_gate[i1 * NTOK + p1] = g1;
        int p2 = atomicAdd(&g_counts[i2], 1);
        g_tok [i2 * NTOK + p2] = gwarp;
        g_gate[i2 * NTOK + p2] = g2;
    }
}

// ============================================================
// Kernel 2: grouped GEMM #1 — hidden = gelu(x[toks] @ Wd[e] + bd[e])
// M = n_e (ragged), N = HDIM, K = DDIM. 64x64 tile, 256 threads, 4x4/thread.
// ============================================================
__global__ __launch_bounds__(256) void expert_down_kernel(
    const float* __restrict__ x, const float* __restrict__ Wd, const float* __restrict__ bd)
{
    int e  = blockIdx.z;
    int ne = g_counts[e];
    int m0 = blockIdx.y * 64;
    if (m0 >= ne) return;
    int n0 = blockIdx.x * 64;

    __shared__ float As[16][68];   // [k][m], pad to keep float4 alignment
    __shared__ float Bs[16][64];   // [k][n]

    int tid = threadIdx.x;
    int ty = tid >> 4;       // 0..15 -> m groups of 4
    int tx = tid & 15;       // 0..15 -> n groups of 4

    // A-tile load mapping: 64 rows x 16 k, one float4 per thread
    int am = tid >> 2;            // 0..63
    int ak = (tid & 3) * 4;       // 0,4,8,12
    int arow = m0 + am;
    bool aval = arow < ne;
    int tokA = aval ? g_tok[e * NTOK + arow] : 0;
    const float* aRowPtr = x + (size_t)tokA * DDIM;

    // B-tile load mapping: 16 rows x 64 n
    int bk = tid >> 4;            // 0..15
    int bn_ = (tid & 15) * 4;
    const float* Wde = Wd + (size_t)e * DDIM * HDIM;

    float acc[4][4];
#pragma unroll
    for (int i = 0; i < 4; i++)
#pragma unroll
        for (int j = 0; j < 4; j++) acc[i][j] = 0.f;

    for (int k0 = 0; k0 < DDIM; k0 += 16) {
        float4 av = make_float4(0.f, 0.f, 0.f, 0.f);
        if (aval) av = *(const float4*)(aRowPtr + k0 + ak);
        As[ak + 0][am] = av.x;
        As[ak + 1][am] = av.y;
        As[ak + 2][am] = av.z;
        As[ak + 3][am] = av.w;
        *(float4*)&Bs[bk][bn_] =
            *(const float4*)(Wde + (size_t)(k0 + bk) * HDIM + n0 + bn_);
        __syncthreads();
#pragma unroll
        for (int k = 0; k < 16; k++) {
            float4 a = *(const float4*)&As[k][ty * 4];
            float4 b = *(const float4*)&Bs[k][tx * 4];
            acc[0][0] = fmaf(a.x, b.x, acc[0][0]);
            acc[0][1] = fmaf(a.x, b.y, acc[0][1]);
            acc[0][2] = fmaf(a.x, b.z, acc[0][2]);
            acc[0][3] = fmaf(a.x, b.w, acc[0][3]);
            acc[1][0] = fmaf(a.y, b.x, acc[1][0]);
            acc[1][1] = fmaf(a.y, b.y, acc[1][1]);
            acc[1][2] = fmaf(a.y, b.z, acc[1][2]);
            acc[1][3] = fmaf(a.y, b.w, acc[1][3]);
            acc[2][0] = fmaf(a.z, b.x, acc[2][0]);
            acc[2][1] = fmaf(a.z, b.y, acc[2][1]);
            acc[2][2] = fmaf(a.z, b.z, acc[2][2]);
            acc[2][3] = fmaf(a.z, b.w, acc[2][3]);
            acc[3][0] = fmaf(a.w, b.x, acc[3][0]);
            acc[3][1] = fmaf(a.w, b.y, acc[3][1]);
            acc[3][2] = fmaf(a.w, b.z, acc[3][2]);
            acc[3][3] = fmaf(a.w, b.w, acc[3][3]);
        }
        __syncthreads();
    }

#pragma unroll
    for (int i = 0; i < 4; i++) {
        int m = m0 + ty * 4 + i;
        if (m >= ne) continue;
        float* hrow = g_hidden + ((size_t)e * NTOK + m) * HDIM;
#pragma unroll
        for (int j = 0; j < 4; j++) {
            int n = n0 + tx * 4 + j;
            float h = acc[i][j] + bd[e * HDIM + n];
            // exact (erf) GELU
            h = 0.5f * h * (1.0f + erff(h * 0.70710678118654752f));
            hrow[n] = h;
        }
    }
}

// ============================================================
// Kernel 3: grouped GEMM #2 — out[tok] += gate * (hidden @ Wu[e] + bu[e])
// M = n_e, N = DDIM, K = HDIM.
// ============================================================
__global__ __launch_bounds__(256) void expert_up_kernel(
    const float* __restrict__ Wu, const float* __restrict__ bu, float* __restrict__ out)
{
    int e  = blockIdx.z;
    int ne = g_counts[e];
    int m0 = blockIdx.y * 64;
    if (m0 >= ne) return;
    int n0 = blockIdx.x * 64;

    __shared__ float As[16][68];
    __shared__ float Bs[16][64];

    int tid = threadIdx.x;
    int ty = tid >> 4;
    int tx = tid & 15;

    int am = tid >> 2;
    int ak = (tid & 3) * 4;
    int arow = m0 + am;
    bool aval = arow < ne;
    const float* aRowPtr = g_hidden + ((size_t)e * NTOK + (aval ? arow : 0)) * HDIM;

    int bk = tid >> 4;
    int bn_ = (tid & 15) * 4;
    const float* Wue = Wu + (size_t)e * HDIM * DDIM;

    float acc[4][4];
#pragma unroll
    for (int i = 0; i < 4; i++)
#pragma unroll
        for (int j = 0; j < 4; j++) acc[i][j] = 0.f;

    for (int k0 = 0; k0 < HDIM; k0 += 16) {
        float4 av = make_float4(0.f, 0.f, 0.f, 0.f);
        if (aval) av = *(const float4*)(aRowPtr + k0 + ak);
        As[ak + 0][am] = av.x;
        As[ak + 1][am] = av.y;
        As[ak + 2][am] = av.z;
        As[ak + 3][am] = av.w;
        *(float4*)&Bs[bk][bn_] =
            *(const float4*)(Wue + (size_t)(k0 + bk) * DDIM + n0 + bn_);
        __syncthreads();
#pragma unroll
        for (int k = 0; k < 16; k++) {
            float4 a = *(const float4*)&As[k][ty * 4];
            float4 b = *(const float4*)&Bs[k][tx * 4];
            acc[0][0] = fmaf(a.x, b.x, acc[0][0]);
            acc[0][1] = fmaf(a.x, b.y, acc[0][1]);
            acc[0][2] = fmaf(a.x, b.z, acc[0][2]);
            acc[0][3] = fmaf(a.x, b.w, acc[0][3]);
            acc[1][0] = fmaf(a.y, b.x, acc[1][0]);
            acc[1][1] = fmaf(a.y, b.y, acc[1][1]);
            acc[1][2] = fmaf(a.y, b.z, acc[1][2]);
            acc[1][3] = fmaf(a.y, b.w, acc[1][3]);
            acc[2][0] = fmaf(a.z, b.x, acc[2][0]);
            acc[2][1] = fmaf(a.z, b.y, acc[2][1]);
            acc[2][2] = fmaf(a.z, b.z, acc[2][2]);
            acc[2][3] = fmaf(a.z, b.w, acc[2][3]);
            acc[3][0] = fmaf(a.w, b.x, acc[3][0]);
            acc[3][1] = fmaf(a.w, b.y, acc[3][1]);
            acc[3][2] = fmaf(a.w, b.z, acc[3][2]);
            acc[3][3] = fmaf(a.w, b.w, acc[3][3]);
        }
        __syncthreads();
    }

#pragma unroll
    for (int i = 0; i < 4; i++) {
        int m = m0 + ty * 4 + i;
        if (m >= ne) continue;
        int   tok = g_tok [e * NTOK + m];
        float g   = g_gate[e * NTOK + m];
        float* orow = out + (size_t)tok * DDIM;
#pragma unroll
        for (int j = 0; j < 4; j++) {
            int n = n0 + tx * 4 + j;
            float v = (acc[i][j] + bu[e * DDIM + n]) * g;
            atomicAdd(&orow[n], v);   // exactly 2 commutative adds per element -> deterministic
        }
    }
}

// ============================================================
// Host launcher
// ============================================================
extern "C" void kernel_launch(void* const* d_in, const int* in_sizes, int n_in,
                              void* d_out, int out_size) {
    const float* x     = (const float*)d_in[0];
    const float* Wr    = (const float*)d_in[1];
    const float* br    = (const float*)d_in[2];
    const float* Wn    = (const float*)d_in[3];
    const float* bn    = (const float*)d_in[4];
    const float* Wd    = (const float*)d_in[5];
    const float* bd    = (const float*)d_in[6];
    const float* Wu    = (const float*)d_in[7];
    const float* bu    = (const float*)d_in[8];
    const float* noise = (const float*)d_in[9];
    float* out = (float*)d_out;

    // zero output + counters
    init_kernel<<<(NTOK * DDIM / 4 + 255) / 256, 256>>>(out);

    // router: 1 warp per token
    router_kernel<<<NTOK / 8, 256>>>(x, Wr, br, Wn, bn, noise);

    // expert down-projection + GELU
    expert_down_kernel<<<dim3(HDIM / 64, NTOK / 64, NEXP), 256>>>(x, Wd, bd);

    // expert up-projection + gate-weighted scatter
    expert_up_kernel<<<dim3(DDIM / 64, NTOK / 64, NEXP), 256>>>(Wu, bu, out);
}

// round 2
// speedup vs baseline: 3.0073x; 3.0073x over previous
#include <cuda_runtime.h>
#include <math.h>
#include <stdint.h>

#define NTOK 16384   // B*T = 4*4096
#define DDIM 1024
#define NEXP 8
#define HDIM 512

#define BM 128
#define BN 128
#define BK 32

// ---- device scratch ----
__device__ int   g_counts[NEXP];
__device__ int   g_tok [NEXP * NTOK];
__device__ float g_gate[NEXP * NTOK];
__device__ float g_hidden[(size_t)NEXP * NTOK * HDIM];   // worst-case capacity

// ============================================================
// helpers
// ============================================================
__device__ __forceinline__ uint32_t f2tf32(float f) {
    uint32_t u;
    asm("cvt.rna.tf32.f32 %0, %1;" : "=r"(u) : "f"(f));
    return u;
}

__device__ __forceinline__ void mma_tf32(float c[4],
                                         uint32_t a0, uint32_t a1, uint32_t a2, uint32_t a3,
                                         uint32_t b0, uint32_t b1) {
    asm volatile(
        "mma.sync.aligned.m16n8k8.row.col.f32.tf32.tf32.f32 "
        "{%0,%1,%2,%3}, {%4,%5,%6,%7}, {%8,%9}, {%0,%1,%2,%3};"
        : "+f"(c[0]), "+f"(c[1]), "+f"(c[2]), "+f"(c[3])
        : "r"(a0), "r"(a1), "r"(a2), "r"(a3), "r"(b0), "r"(b1));
}

// ============================================================
// Kernel 0: zero output + counters
// ============================================================
__global__ void init_kernel(float* __restrict__ out) {
    size_t i = (size_t)blockIdx.x * blockDim.x + threadIdx.x;
    if (i < (size_t)NTOK * DDIM / 4) {
        ((float4*)out)[i] = make_float4(0.f, 0.f, 0.f, 0.f);
    }
    if (blockIdx.x == 0 && threadIdx.x < NEXP) g_counts[threadIdx.x] = 0;
}

// ============================================================
// Kernel 1: router — one warp per token
// ============================================================
__global__ void router_kernel(const float* __restrict__ x,
                              const float* __restrict__ Wr, const float* __restrict__ br,
                              const float* __restrict__ Wn, const float* __restrict__ bn,
                              const float* __restrict__ noise) {
    int gwarp = (blockIdx.x * blockDim.x + threadIdx.x) >> 5;
    int lane  = threadIdx.x & 31;
    if (gwarp >= NTOK) return;
    const float* xr = x + (size_t)gwarp * DDIM;

    float accL[NEXP], accN[NEXP];
#pragma unroll
    for (int e = 0; e < NEXP; e++) { accL[e] = 0.f; accN[e] = 0.f; }

    for (int d = lane; d < DDIM; d += 32) {
        float  xv = xr[d];
        float4 r0 = ((const float4*)(Wr + (size_t)d * NEXP))[0];
        float4 r1 = ((const float4*)(Wr + (size_t)d * NEXP))[1];
        float4 n0 = ((const float4*)(Wn + (size_t)d * NEXP))[0];
        float4 n1 = ((const float4*)(Wn + (size_t)d * NEXP))[1];
        accL[0] = fmaf(xv, r0.x, accL[0]);
        accL[1] = fmaf(xv, r0.y, accL[1]);
        accL[2] = fmaf(xv, r0.z, accL[2]);
        accL[3] = fmaf(xv, r0.w, accL[3]);
        accL[4] = fmaf(xv, r1.x, accL[4]);
        accL[5] = fmaf(xv, r1.y, accL[5]);
        accL[6] = fmaf(xv, r1.z, accL[6]);
        accL[7] = fmaf(xv, r1.w, accL[7]);
        accN[0] = fmaf(xv, n0.x, accN[0]);
        accN[1] = fmaf(xv, n0.y, accN[1]);
        accN[2] = fmaf(xv, n0.z, accN[2]);
        accN[3] = fmaf(xv, n0.w, accN[3]);
        accN[4] = fmaf(xv, n1.x, accN[4]);
        accN[5] = fmaf(xv, n1.y, accN[5]);
        accN[6] = fmaf(xv, n1.z, accN[6]);
        accN[7] = fmaf(xv, n1.w, accN[7]);
    }

#pragma unroll
    for (int off = 16; off > 0; off >>= 1) {
#pragma unroll
        for (int e = 0; e < NEXP; e++) {
            accL[e] += __shfl_down_sync(0xffffffffu, accL[e], off);
            accN[e] += __shfl_down_sync(0xffffffffu, accN[e], off);
        }
    }

    if (lane == 0) {
        float noisy[NEXP];
#pragma unroll
        for (int e = 0; e < NEXP; e++) {
            float nl = accN[e] + bn[e];
            float sp = fmaxf(nl, 0.f) + log1pf(expf(-fabsf(nl)));
            noisy[e] = accL[e] + br[e] + noise[(size_t)gwarp * NEXP + e] * sp;
        }
        int i1 = 0; float v1 = noisy[0];
#pragma unroll
        for (int e = 1; e < NEXP; e++) if (noisy[e] > v1) { v1 = noisy[e]; i1 = e; }
        int i2 = -1; float v2 = -3.4e38f;
#pragma unroll
        for (int e = 0; e < NEXP; e++) if (e != i1 && noisy[e] > v2) { v2 = noisy[e]; i2 = e; }

        float e2 = expf(v2 - v1);
        float s  = 1.0f + e2;
        float g1 = 1.0f / s;
        float g2 = e2 / s;

        int p1 = atomicAdd(&g_counts[i1], 1);
        g_tok [i1 * NTOK + p1] = gwarp;
        g_gate[i1 * NTOK + p1] = g1;
        int p2 = atomicAdd(&g_counts[i2], 1);
        g_tok [i2 * NTOK + p2] = gwarp;
        g_gate[i2 * NTOK + p2] = g2;
    }
}

// ============================================================
// Kernel 2: grouped GEMM #1 (tf32 tensor cores)
// hidden = gelu(x[toks] @ Wd[e] + bd[e]);  M=ne, N=HDIM, K=DDIM
// ============================================================
__global__ __launch_bounds__(256, 2) void expert_down_mma(
    const float* __restrict__ x, const float* __restrict__ Wd, const float* __restrict__ bd)
{
    int e  = blockIdx.z;
    int ne = g_counts[e];
    int m0 = blockIdx.y * BM;
    if (m0 >= ne) return;
    int n0 = blockIdx.x * BN;

    __shared__ uint32_t As[BM][36];                       // conflict-free frag loads
    __shared__ __align__(16) uint32_t Bs[BK][136];        // conflict-free frag loads + uint4 stores

    int tid  = threadIdx.x;
    int lane = tid & 31;
    int wid  = tid >> 5;
    int warp_m = (wid & 3) * 32;      // 4 warps over M
    int warp_n = (wid >> 2) * 64;     // 2 warps over N
    int g = lane >> 2, t = lane & 3;

    // A load mapping: 128 rows x 8 float4; 4 rows per thread
    int arow_r = tid >> 3;   // 0..31
    int akq    = tid & 7;    // float4 within row
    const float* aptr[4];
    bool avalid[4];
#pragma unroll
    for (int i = 0; i < 4; i++) {
        int m = m0 + i * 32 + arow_r;
        avalid[i] = m < ne;
        int tok = avalid[i] ? g_tok[e * NTOK + m] : 0;
        aptr[i] = x + (size_t)tok * DDIM + akq * 4;
    }
    const float* Wde = Wd + (size_t)e * DDIM * HDIM;

    float acc[2][8][4];
#pragma unroll
    for (int mi = 0; mi < 2; mi++)
#pragma unroll
        for (int ni = 0; ni < 8; ni++)
#pragma unroll
            for (int j = 0; j < 4; j++) acc[mi][ni][j] = 0.f;

    for (int k0 = 0; k0 < DDIM; k0 += BK) {
#pragma unroll
        for (int i = 0; i < 4; i++) {
            int r = i * 32 + arow_r;
            float4 v = avalid[i] ? *(const float4*)(aptr[i] + k0) : make_float4(0.f,0.f,0.f,0.f);
            As[r][akq*4+0] = f2tf32(v.x);
            As[r][akq*4+1] = f2tf32(v.y);
            As[r][akq*4+2] = f2tf32(v.z);
            As[r][akq*4+3] = f2tf32(v.w);
        }
#pragma unroll
        for (int i = 0; i < 4; i++) {
            int f  = i * 256 + tid;
            int kr = f >> 5, c = f & 31;
            float4 v = *(const float4*)(Wde + (size_t)(k0 + kr) * HDIM + n0 + c * 4);
            uint4 u;
            u.x = f2tf32(v.x); u.y = f2tf32(v.y); u.z = f2tf32(v.z); u.w = f2tf32(v.w);
            *(uint4*)&Bs[kr][c * 4] = u;
        }
        __syncthreads();

#pragma unroll
        for (int ks = 0; ks < 4; ks++) {
            int kk = ks * 8;
            uint32_t af[2][4];
#pragma unroll
            for (int mi = 0; mi < 2; mi++) {
                int mr = warp_m + mi * 16 + g;
                af[mi][0] = As[mr    ][kk + t];
                af[mi][1] = As[mr + 8][kk + t];
                af[mi][2] = As[mr    ][kk + t + 4];
                af[mi][3] = As[mr + 8][kk + t + 4];
            }
#pragma unroll
            for (int ni = 0; ni < 8; ni++) {
                uint32_t b0 = Bs[kk + t    ][warp_n + ni * 8 + g];
                uint32_t b1 = Bs[kk + t + 4][warp_n + ni * 8 + g];
                mma_tf32(acc[0][ni], af[0][0], af[0][1], af[0][2], af[0][3], b0, b1);
                mma_tf32(acc[1][ni], af[1][0], af[1][1], af[1][2], af[1][3], b0, b1);
            }
        }
        __syncthreads();
    }

    // epilogue: bias + exact GELU, write hidden (float2 per pair)
#pragma unroll
    for (int mi = 0; mi < 2; mi++) {
        int m1 = m0 + warp_m + mi * 16 + g;
        int m2 = m1 + 8;
#pragma unroll
        for (int ni = 0; ni < 8; ni++) {
            int n = n0 + warp_n + ni * 8 + 2 * t;
            float b0v = bd[e * HDIM + n];
            float b1v = bd[e * HDIM + n + 1];
            if (m1 < ne) {
                float h0 = acc[mi][ni][0] + b0v;
                float h1 = acc[mi][ni][1] + b1v;
                h0 = 0.5f * h0 * (1.0f + erff(h0 * 0.70710678118654752f));
                h1 = 0.5f * h1 * (1.0f + erff(h1 * 0.70710678118654752f));
                *(float2*)(g_hidden + ((size_t)e * NTOK + m1) * HDIM + n) = make_float2(h0, h1);
            }
            if (m2 < ne) {
                float h2 = acc[mi][ni][2] + b0v;
                float h3 = acc[mi][ni][3] + b1v;
                h2 = 0.5f * h2 * (1.0f + erff(h2 * 0.70710678118654752f));
                h3 = 0.5f * h3 * (1.0f + erff(h3 * 0.70710678118654752f));
                *(float2*)(g_hidden + ((size_t)e * NTOK + m2) * HDIM + n) = make_float2(h2, h3);
            }
        }
    }
}

// ============================================================
// Kernel 3: grouped GEMM #2 (tf32 tensor cores)
// out[tok] += gate * (hidden @ Wu[e] + bu[e]);  M=ne, N=DDIM, K=HDIM
// ============================================================
__global__ __launch_bounds__(256, 2) void expert_up_mma(
    const float* __restrict__ Wu, const float* __restrict__ bu, float* __restrict__ out)
{
    int e  = blockIdx.z;
    int ne = g_counts[e];
    int m0 = blockIdx.y * BM;
    if (m0 >= ne) return;
    int n0 = blockIdx.x * BN;

    __shared__ uint32_t As[BM][36];
    __shared__ __align__(16) uint32_t Bs[BK][136];

    int tid  = threadIdx.x;
    int lane = tid & 31;
    int wid  = tid >> 5;
    int warp_m = (wid & 3) * 32;
    int warp_n = (wid >> 2) * 64;
    int g = lane >> 2, t = lane & 3;

    int arow_r = tid >> 3;
    int akq    = tid & 7;
    const float* aptr[4];
    bool avalid[4];
#pragma unroll
    for (int i = 0; i < 4; i++) {
        int m = m0 + i * 32 + arow_r;
        avalid[i] = m < ne;
        int mm = avalid[i] ? m : 0;
        aptr[i] = g_hidden + ((size_t)e * NTOK + mm) * HDIM + akq * 4;
    }
    const float* Wue = Wu + (size_t)e * HDIM * DDIM;

    float acc[2][8][4];
#pragma unroll
    for (int mi = 0; mi < 2; mi++)
#pragma unroll
        for (int ni = 0; ni < 8; ni++)
#pragma unroll
            for (int j = 0; j < 4; j++) acc[mi][ni][j] = 0.f;

    for (int k0 = 0; k0 < HDIM; k0 += BK) {
#pragma unroll
        for (int i = 0; i < 4; i++) {
            int r = i * 32 + arow_r;
            float4 v = avalid[i] ? *(const float4*)(aptr[i] + k0) : make_float4(0.f,0.f,0.f,0.f);
            As[r][akq*4+0] = f2tf32(v.x);
            As[r][akq*4+1] = f2tf32(v.y);
            As[r][akq*4+2] = f2tf32(v.z);
            As[r][akq*4+3] = f2tf32(v.w);
        }
#pragma unroll
        for (int i = 0; i < 4; i++) {
            int f  = i * 256 + tid;
            int kr = f >> 5, c = f & 31;
            float4 v = *(const float4*)(Wue + (size_t)(k0 + kr) * DDIM + n0 + c * 4);
            uint4 u;
            u.x = f2tf32(v.x); u.y = f2tf32(v.y); u.z = f2tf32(v.z); u.w = f2tf32(v.w);
            *(uint4*)&Bs[kr][c * 4] = u;
        }
        __syncthreads();

#pragma unroll
        for (int ks = 0; ks < 4; ks++) {
            int kk = ks * 8;
            uint32_t af[2][4];
#pragma unroll
            for (int mi = 0; mi < 2; mi++) {
                int mr = warp_m + mi * 16 + g;
                af[mi][0] = As[mr    ][kk + t];
                af[mi][1] = As[mr + 8][kk + t];
                af[mi][2] = As[mr    ][kk + t + 4];
                af[mi][3] = As[mr + 8][kk + t + 4];
            }
#pragma unroll
            for (int ni = 0; ni < 8; ni++) {
                uint32_t b0 = Bs[kk + t    ][warp_n + ni * 8 + g];
                uint32_t b1 = Bs[kk + t + 4][warp_n + ni * 8 + g];
                mma_tf32(acc[0][ni], af[0][0], af[0][1], af[0][2], af[0][3], b0, b1);
                mma_tf32(acc[1][ni], af[1][0], af[1][1], af[1][2], af[1][3], b0, b1);
            }
        }
        __syncthreads();
    }

    // epilogue: bias + gate * atomicAdd scatter (2 commutative adds/element -> deterministic)
#pragma unroll
    for (int mi = 0; mi < 2; mi++) {
        int m1 = m0 + warp_m + mi * 16 + g;
        int m2 = m1 + 8;
        int   tok1 = 0, tok2 = 0;
        float gt1 = 0.f, gt2 = 0.f;
        if (m1 < ne) { tok1 = g_tok[e * NTOK + m1]; gt1 = g_gate[e * NTOK + m1]; }
        if (m2 < ne) { tok2 = g_tok[e * NTOK + m2]; gt2 = g_gate[e * NTOK + m2]; }
#pragma unroll
        for (int ni = 0; ni < 8; ni++) {
            int n = n0 + warp_n + ni * 8 + 2 * t;
            float b0v = bu[e * DDIM + n];
            float b1v = bu[e * DDIM + n + 1];
            if (m1 < ne) {
                atomicAdd(out + (size_t)tok1 * DDIM + n,     (acc[mi][ni][0] + b0v) * gt1);
                atomicAdd(out + (size_t)tok1 * DDIM + n + 1, (acc[mi][ni][1] + b1v) * gt1);
            }
            if (m2 < ne) {
                atomicAdd(out + (size_t)tok2 * DDIM + n,     (acc[mi][ni][2] + b0v) * gt2);
                atomicAdd(out + (size_t)tok2 * DDIM + n + 1, (acc[mi][ni][3] + b1v) * gt2);
            }
        }
    }
}

// ============================================================
// Host launcher
// ============================================================
extern "C" void kernel_launch(void* const* d_in, const int* in_sizes, int n_in,
                              void* d_out, int out_size) {
    const float* x     = (const float*)d_in[0];
    const float* Wr    = (const float*)d_in[1];
    const float* br    = (const float*)d_in[2];
    const float* Wn    = (const float*)d_in[3];
    const float* bn    = (const float*)d_in[4];
    const float* Wd    = (const float*)d_in[5];
    const float* bd    = (const float*)d_in[6];
    const float* Wu    = (const float*)d_in[7];
    const float* bu    = (const float*)d_in[8];
    const float* noise = (const float*)d_in[9];
    float* out = (float*)d_out;

    init_kernel<<<(NTOK * DDIM / 4 + 255) / 256, 256>>>(out);
    router_kernel<<<NTOK / 8, 256>>>(x, Wr, br, Wn, bn, noise);
    expert_down_mma<<<dim3(HDIM / BN, NTOK / BM, NEXP), 256>>>(x, Wd, bd);
    expert_up_mma<<<dim3(DDIM / BN, NTOK / BM, NEXP), 256>>>(Wu, bu, out);
}

// round 5
// speedup vs baseline: 3.3021x; 1.0980x over previous
#include <cuda_runtime.h>
#include <math.h>
#include <stdint.h>

#define NTOK 16384   // B*T
#define DDIM 1024
#define NEXP 8
#define HDIM 512

#define BM 128
#define BN 128
#define BK 32

// ---------------- device scratch ----------------
__device__ int   g_counts[NEXP];
__device__ int   g_tok [NEXP * NTOK];
__device__ float g_gate[NEXP * NTOK];
__device__ float g_xr  [(size_t)NTOK * DDIM];            // tf32-rounded x
__device__ float g_Wdr [(size_t)NEXP * DDIM * HDIM];     // tf32-rounded Wd [e][k][n]
__device__ float g_Wur [(size_t)NEXP * HDIM * DDIM];     // tf32-rounded Wu [e][k][n]
__device__ float g_hidden[(size_t)NEXP * NTOK * HDIM];   // tf32-rounded gelu output

// ---------------- helpers ----------------
__device__ __forceinline__ float tf32r(float f) {
    uint32_t u;
    asm("cvt.rna.tf32.f32 %0, %1;" : "=r"(u) : "f"(f));
    return __uint_as_float(u);
}
__device__ __forceinline__ void mma_tf32(float c[4],
                                         uint32_t a0, uint32_t a1, uint32_t a2, uint32_t a3,
                                         uint32_t b0, uint32_t b1) {
    asm volatile(
        "mma.sync.aligned.m16n8k8.row.col.f32.tf32.tf32.f32 "
        "{%0,%1,%2,%3}, {%4,%5,%6,%7}, {%8,%9}, {%0,%1,%2,%3};"
        : "+f"(c[0]), "+f"(c[1]), "+f"(c[2]), "+f"(c[3])
        : "r"(a0), "r"(a1), "r"(a2), "r"(a3), "r"(b0), "r"(b1));
}
__device__ __forceinline__ void cp16(uint32_t dst, const void* src) {
    asm volatile("cp.async.cg.shared.global [%0], [%1], 16;" :: "r"(dst), "l"(src));
}
#define CP_COMMIT() asm volatile("cp.async.commit_group;" ::: "memory")
#define CP_WAIT(n)  asm volatile("cp.async.wait_group %0;" :: "n"(n) : "memory")

// padded smem strides (floats): A row 36, B row 136 -> conflict-free frag loads
#define ASTRIDE 36
#define BSTRIDE 136
#define A_TILE_BYTES (BM * ASTRIDE * 4)        // 18432
#define B_TILE_BYTES (BK * BSTRIDE * 4)        // 17408
#define STAGE_BYTES  (A_TILE_BYTES + B_TILE_BYTES)
#define SMEM_BYTES   (2 * STAGE_BYTES)         // 71680

// ============================================================
// Kernel 0: zero output + counters
// ============================================================
__global__ void init_kernel(float* __restrict__ out) {
    size_t i = (size_t)blockIdx.x * blockDim.x + threadIdx.x;
    if (i < (size_t)NTOK * DDIM / 4)
        ((float4*)out)[i] = make_float4(0.f, 0.f, 0.f, 0.f);
    if (blockIdx.x == 0 && threadIdx.x < NEXP) g_counts[threadIdx.x] = 0;
}

// ============================================================
// prep: tf32 rounding into device-symbol scratch (NO device symbols
// may cross the host launch boundary — reference them here directly)
// ============================================================
__global__ void round_x_kernel(const float* __restrict__ src) {
    size_t i = (size_t)blockIdx.x * blockDim.x + threadIdx.x;
    float4 v = ((const float4*)src)[i];
    v.x = tf32r(v.x); v.y = tf32r(v.y); v.z = tf32r(v.z); v.w = tf32r(v.w);
    ((float4*)g_xr)[i] = v;
}
__global__ void round_wd_kernel(const float* __restrict__ src) {
    size_t i = (size_t)blockIdx.x * blockDim.x + threadIdx.x;
    float4 v = ((const float4*)src)[i];
    v.x = tf32r(v.x); v.y = tf32r(v.y); v.z = tf32r(v.z); v.w = tf32r(v.w);
    ((float4*)g_Wdr)[i] = v;
}
__global__ void round_wu_kernel(const float* __restrict__ src) {
    size_t i = (size_t)blockIdx.x * blockDim.x + threadIdx.x;
    float4 v = ((const float4*)src)[i];
    v.x = tf32r(v.x); v.y = tf32r(v.y); v.z = tf32r(v.z); v.w = tf32r(v.w);
    ((float4*)g_Wur)[i] = v;
}

// ============================================================
// router — one warp per token
// ============================================================
__global__ void router_kernel(const float* __restrict__ x,
                              const float* __restrict__ Wr, const float* __restrict__ br,
                              const float* __restrict__ Wn, const float* __restrict__ bn,
                              const float* __restrict__ noise) {
    int gwarp = (blockIdx.x * blockDim.x + threadIdx.x) >> 5;
    int lane  = threadIdx.x & 31;
    if (gwarp >= NTOK) return;
    const float* xr = x + (size_t)gwarp * DDIM;

    float accL[NEXP], accN[NEXP];
#pragma unroll
    for (int e = 0; e < NEXP; e++) { accL[e] = 0.f; accN[e] = 0.f; }

    for (int d = lane; d < DDIM; d += 32) {
        float  xv = xr[d];
        float4 r0 = ((const float4*)(Wr + (size_t)d * NEXP))[0];
        float4 r1 = ((const float4*)(Wr + (size_t)d * NEXP))[1];
        float4 n0 = ((const float4*)(Wn + (size_t)d * NEXP))[0];
        float4 n1 = ((const float4*)(Wn + (size_t)d * NEXP))[1];
        accL[0] = fmaf(xv, r0.x, accL[0]); accL[1] = fmaf(xv, r0.y, accL[1]);
        accL[2] = fmaf(xv, r0.z, accL[2]); accL[3] = fmaf(xv, r0.w, accL[3]);
        accL[4] = fmaf(xv, r1.x, accL[4]); accL[5] = fmaf(xv, r1.y, accL[5]);
        accL[6] = fmaf(xv, r1.z, accL[6]); accL[7] = fmaf(xv, r1.w, accL[7]);
        accN[0] = fmaf(xv, n0.x, accN[0]); accN[1] = fmaf(xv, n0.y, accN[1]);
        accN[2] = fmaf(xv, n0.z, accN[2]); accN[3] = fmaf(xv, n0.w, accN[3]);
        accN[4] = fmaf(xv, n1.x, accN[4]); accN[5] = fmaf(xv, n1.y, accN[5]);
        accN[6] = fmaf(xv, n1.z, accN[6]); accN[7] = fmaf(xv, n1.w, accN[7]);
    }
#pragma unroll
    for (int off = 16; off > 0; off >>= 1) {
#pragma unroll
        for (int e = 0; e < NEXP; e++) {
            accL[e] += __shfl_down_sync(0xffffffffu, accL[e], off);
            accN[e] += __shfl_down_sync(0xffffffffu, accN[e], off);
        }
    }
    if (lane == 0) {
        float noisy[NEXP];
#pragma unroll
        for (int e = 0; e < NEXP; e++) {
            float nl = accN[e] + bn[e];
            float sp = fmaxf(nl, 0.f) + log1pf(expf(-fabsf(nl)));
            noisy[e] = accL[e] + br[e] + noise[(size_t)gwarp * NEXP + e] * sp;
        }
        int i1 = 0; float v1 = noisy[0];
#pragma unroll
        for (int e = 1; e < NEXP; e++) if (noisy[e] > v1) { v1 = noisy[e]; i1 = e; }
        int i2 = -1; float v2 = -3.4e38f;
#pragma unroll
        for (int e = 0; e < NEXP; e++) if (e != i1 && noisy[e] > v2) { v2 = noisy[e]; i2 = e; }

        float e2 = expf(v2 - v1);
        float s  = 1.0f + e2;
        float g1 = 1.0f / s;
        float g2 = e2 / s;

        int p1 = atomicAdd(&g_counts[i1], 1);
        g_tok [i1 * NTOK + p1] = gwarp;
        g_gate[i1 * NTOK + p1] = g1;
        int p2 = atomicAdd(&g_counts[i2], 1);
        g_tok [i2 * NTOK + p2] = gwarp;
        g_gate[i2 * NTOK + p2] = g2;
    }
}

// ============================================================
// pipelined tile loader (both GEMMs share this shape)
// A: 128 rows x 32 cols (gathered rows), B: 32 rows x 128 cols
// ============================================================
struct TileSrc {
    const float* arow[4];   // per-thread gathered A row base (+ c16*4 applied)
    const float* bsrc;      // B tile base: W + n0 (row k stride = ncols)
    int          bstride;
};

__device__ __forceinline__ void load_stage(char* smem, int stage, const TileSrc& ts,
                                           int k0, int tid) {
    char* As = smem + stage * STAGE_BYTES;
    char* Bs = As + A_TILE_BYTES;
    uint32_t as_u = (uint32_t)__cvta_generic_to_shared(As);
    uint32_t bs_u = (uint32_t)__cvta_generic_to_shared(Bs);
    int c16 = tid & 7;
#pragma unroll
    for (int j = 0; j < 4; j++) {
        int row = (tid >> 3) + 32 * j;
        cp16(as_u + row * (ASTRIDE * 4) + c16 * 16, ts.arow[j] + k0);
    }
    int bcol = tid & 31;
#pragma unroll
    for (int j = 0; j < 4; j++) {
        int k = (tid >> 5) + 8 * j;
        cp16(bs_u + k * (BSTRIDE * 4) + bcol * 16,
             ts.bsrc + (size_t)(k0 + k) * ts.bstride + bcol * 4);
    }
    CP_COMMIT();
}

__device__ __forceinline__ void compute_stage(const char* smem, int stage,
                                              int warp_m, int warp_n, int g, int t,
                                              float acc[2][8][4]) {
    const uint32_t* As = (const uint32_t*)(smem + stage * STAGE_BYTES);
    const uint32_t* Bs = (const uint32_t*)(smem + stage * STAGE_BYTES + A_TILE_BYTES);
#pragma unroll
    for (int ks = 0; ks < 4; ks++) {
        int kk = ks * 8;
        uint32_t af[2][4];
#pragma unroll
        for (int mi = 0; mi < 2; mi++) {
            int mr = warp_m + mi * 16 + g;
            af[mi][0] = As[(mr    ) * ASTRIDE + kk + t];
            af[mi][1] = As[(mr + 8) * ASTRIDE + kk + t];
            af[mi][2] = As[(mr    ) * ASTRIDE + kk + t + 4];
            af[mi][3] = As[(mr + 8) * ASTRIDE + kk + t + 4];
        }
#pragma unroll
        for (int ni = 0; ni < 8; ni++) {
            uint32_t b0 = Bs[(kk + t    ) * BSTRIDE + warp_n + ni * 8 + g];
            uint32_t b1 = Bs[(kk + t + 4) * BSTRIDE + warp_n + ni * 8 + g];
            mma_tf32(acc[0][ni], af[0][0], af[0][1], af[0][2], af[0][3], b0, b1);
            mma_tf32(acc[1][ni], af[1][0], af[1][1], af[1][2], af[1][3], b0, b1);
        }
    }
}

// ============================================================
// Kernel 2: grouped GEMM #1 — hidden = tf32r(gelu(x[toks] @ Wd + bd))
// ============================================================
__global__ __launch_bounds__(256, 2) void expert_down_mma(const float* __restrict__ bd)
{
    extern __shared__ __align__(16) char smem[];
    int e  = blockIdx.z;
    int ne = g_counts[e];
    int m0 = blockIdx.y * BM;
    if (m0 >= ne) return;
    int n0 = blockIdx.x * BN;

    int tid  = threadIdx.x;
    int lane = tid & 31;
    int wid  = tid >> 5;
    int warp_m = (wid & 3) * 32;
    int warp_n = (wid >> 2) * 64;
    int g = lane >> 2, t = lane & 3;

    TileSrc ts;
    int c16 = tid & 7;
#pragma unroll
    for (int j = 0; j < 4; j++) {
        int m = m0 + (tid >> 3) + 32 * j;
        int tok = (m < ne) ? g_tok[e * NTOK + m] : g_tok[e * NTOK + m0];
        ts.arow[j] = g_xr + (size_t)tok * DDIM + c16 * 4;
    }
    ts.bsrc = g_Wdr + (size_t)e * DDIM * HDIM + n0;
    ts.bstride = HDIM;

    float acc[2][8][4];
#pragma unroll
    for (int mi = 0; mi < 2; mi++)
#pragma unroll
        for (int ni = 0; ni < 8; ni++)
#pragma unroll
            for (int j = 0; j < 4; j++) acc[mi][ni][j] = 0.f;

    const int NITER = DDIM / BK;
    load_stage(smem, 0, ts, 0, tid);
    for (int i = 0; i < NITER; i++) {
        if (i + 1 < NITER) {
            load_stage(smem, (i + 1) & 1, ts, (i + 1) * BK, tid);
            CP_WAIT(1);
        } else {
            CP_WAIT(0);
        }
        __syncthreads();
        compute_stage(smem, i & 1, warp_m, warp_n, g, t, acc);
        __syncthreads();
    }

    // epilogue: bias + exact GELU + tf32 round
#pragma unroll
    for (int mi = 0; mi < 2; mi++) {
        int m1 = m0 + warp_m + mi * 16 + g;
        int m2 = m1 + 8;
#pragma unroll
        for (int ni = 0; ni < 8; ni++) {
            int n = n0 + warp_n + ni * 8 + 2 * t;
            float b0v = bd[e * HDIM + n];
            float b1v = bd[e * HDIM + n + 1];
            if (m1 < ne) {
                float h0 = acc[mi][ni][0] + b0v;
                float h1 = acc[mi][ni][1] + b1v;
                h0 = tf32r(0.5f * h0 * (1.0f + erff(h0 * 0.70710678118654752f)));
                h1 = tf32r(0.5f * h1 * (1.0f + erff(h1 * 0.70710678118654752f)));
                *(float2*)(g_hidden + ((size_t)e * NTOK + m1) * HDIM + n) = make_float2(h0, h1);
            }
            if (m2 < ne) {
                float h2 = acc[mi][ni][2] + b0v;
                float h3 = acc[mi][ni][3] + b1v;
                h2 = tf32r(0.5f * h2 * (1.0f + erff(h2 * 0.70710678118654752f)));
                h3 = tf32r(0.5f * h3 * (1.0f + erff(h3 * 0.70710678118654752f)));
                *(float2*)(g_hidden + ((size_t)e * NTOK + m2) * HDIM + n) = make_float2(h2, h3);
            }
        }
    }
}

// ============================================================
// Kernel 3: grouped GEMM #2 — out[tok] += gate * (hidden @ Wu + bu)
// ============================================================
__global__ __launch_bounds__(256, 2) void expert_up_mma(
    const float* __restrict__ bu, float* __restrict__ out)
{
    extern __shared__ __align__(16) char smem[];
    int e  = blockIdx.z;
    int ne = g_counts[e];
    int m0 = blockIdx.y * BM;
    if (m0 >= ne) return;
    int n0 = blockIdx.x * BN;

    int tid  = threadIdx.x;
    int lane = tid & 31;
    int wid  = tid >> 5;
    int warp_m = (wid & 3) * 32;
    int warp_n = (wid >> 2) * 64;
    int g = lane >> 2, t = lane & 3;

    TileSrc ts;
    int c16 = tid & 7;
#pragma unroll
    for (int j = 0; j < 4; j++) {
        int m = m0 + (tid >> 3) + 32 * j;
        int mm = (m < ne) ? m : m0;       // clamp: garbage rows never touch valid accumulators
        ts.arow[j] = g_hidden + ((size_t)e * NTOK + mm) * HDIM + c16 * 4;
    }
    ts.bsrc = g_Wur + (size_t)e * HDIM * DDIM + n0;
    ts.bstride = DDIM;

    float acc[2][8][4];
#pragma unroll
    for (int mi = 0; mi < 2; mi++)
#pragma unroll
        for (int ni = 0; ni < 8; ni++)
#pragma unroll
            for (int j = 0; j < 4; j++) acc[mi][ni][j] = 0.f;

    const int NITER = HDIM / BK;
    load_stage(smem, 0, ts, 0, tid);
    for (int i = 0; i < NITER; i++) {
        if (i + 1 < NITER) {
            load_stage(smem, (i + 1) & 1, ts, (i + 1) * BK, tid);
            CP_WAIT(1);
        } else {
            CP_WAIT(0);
        }
        __syncthreads();
        compute_stage(smem, i & 1, warp_m, warp_n, g, t, acc);
        __syncthreads();
    }

    // epilogue: bias + gate * atomicAdd (2 commutative adds/element -> deterministic)
#pragma unroll
    for (int mi = 0; mi < 2; mi++) {
        int m1 = m0 + warp_m + mi * 16 + g;
        int m2 = m1 + 8;
        int   tok1 = 0, tok2 = 0;
        float gt1 = 0.f, gt2 = 0.f;
        if (m1 < ne) { tok1 = g_tok[e * NTOK + m1]; gt1 = g_gate[e * NTOK + m1]; }
        if (m2 < ne) { tok2 = g_tok[e * NTOK + m2]; gt2 = g_gate[e * NTOK + m2]; }
#pragma unroll
        for (int ni = 0; ni < 8; ni++) {
            int n = n0 + warp_n + ni * 8 + 2 * t;
            float b0v = bu[e * DDIM + n];
            float b1v = bu[e * DDIM + n + 1];
            if (m1 < ne) {
                atomicAdd(out + (size_t)tok1 * DDIM + n,     (acc[mi][ni][0] + b0v) * gt1);
                atomicAdd(out + (size_t)tok1 * DDIM + n + 1, (acc[mi][ni][1] + b1v) * gt1);
            }
            if (m2 < ne) {
                atomicAdd(out + (size_t)tok2 * DDIM + n,     (acc[mi][ni][2] + b0v) * gt2);
                atomicAdd(out + (size_t)tok2 * DDIM + n + 1, (acc[mi][ni][3] + b1v) * gt2);
            }
        }
    }
}

// ============================================================
// Host launcher
// ============================================================
extern "C" void kernel_launch(void* const* d_in, const int* in_sizes, int n_in,
                              void* d_out, int out_size) {
    const float* x     = (const float*)d_in[0];
    const float* Wr    = (const float*)d_in[1];
    const float* br    = (const float*)d_in[2];
    const float* Wn    = (const float*)d_in[3];
    const float* bn    = (const float*)d_in[4];
    const float* Wd    = (const float*)d_in[5];
    const float* bd    = (const float*)d_in[6];
    const float* Wu    = (const float*)d_in[7];
    const float* bu    = (const float*)d_in[8];
    const float* noise = (const float*)d_in[9];
    float* out = (float*)d_out;

    cudaFuncSetAttribute(expert_down_mma, cudaFuncAttributeMaxDynamicSharedMemorySize, SMEM_BYTES);
    cudaFuncSetAttribute(expert_up_mma,   cudaFuncAttributeMaxDynamicSharedMemorySize, SMEM_BYTES);

    init_kernel<<<(NTOK * DDIM / 4 + 255) / 256, 256>>>(out);
    round_x_kernel<<<NTOK * DDIM / 4 / 256, 256>>>(x);
    round_wd_kernel<<<NEXP * DDIM * HDIM / 4 / 256, 256>>>(Wd);
    round_wu_kernel<<<NEXP * HDIM * DDIM / 4 / 256, 256>>>(Wu);
    router_kernel<<<NTOK / 8, 256>>>(x, Wr, br, Wn, bn, noise);
    expert_down_mma<<<dim3(HDIM / BN, NTOK / BM, NEXP), 256, SMEM_BYTES>>>(bd);
    expert_up_mma<<<dim3(DDIM / BN, NTOK / BM, NEXP), 256, SMEM_BYTES>>>(bu, out);
}